// round 15
// baseline (speedup 1.0000x reference)
#include <cuda_runtime.h>
#include <cuda_fp16.h>
#include <cstdint>

// Problem constants (fixed shapes)
#define NN 50000      // nodes
#define EE 1600000    // edges
#define TT 6          // time steps
#define NB 8          // batch
#define NH 16         // hidden

#define CB 1184       // combine blocks (8/SM -> ~full occupancy at 48 regs)
#define CT 256        // combine threads/block

// Scratch (device globals — no allocation allowed).
// g_deg starts zeroed (module load) and is RE-ZEROED by k_dinv each run,
// so the graph needs no memset node. Same self-cleaning pattern as g_acch.
__device__ int          g_deg[NN];
__device__ float        g_dinv[NN];
__device__ float4       g_xt[NN * 2];      // x[b, T-1, n] transposed to [n][8] (fp32)
__device__ uint4        g_gth[NN];         // dinv[n] * xt[n][b], packed 8 x f16
__device__ uint4        g_acch[NN];        // scatter accumulator, 8 x f16 per node
__device__ float        g_part[CB * 128];  // per-block partial (b,h) sums

// ---------------------------------------------------------------------------
__device__ __forceinline__ float tanh_fast(float x) {
    float y;
    asm("tanh.approx.f32 %0, %1;" : "=f"(y) : "f"(x));
    return y;
}

__device__ __forceinline__ void red_add_v4h2(uint4* addr, uint4 v) {
    asm volatile("red.global.add.noftz.v4.f16x2 [%0], {%1, %2, %3, %4};"
                 :: "l"(addr), "r"(v.x), "r"(v.y), "r"(v.z), "r"(v.w)
                 : "memory");
}

// ---------------------------------------------------------------------------
// K1: degree histogram (src column) + transpose last-timestep x to [n][8]
__global__ void k_deg_xt(const int* __restrict__ ei, const float* __restrict__ x) {
    int i = blockIdx.x * blockDim.x + threadIdx.x;
    int stride = gridDim.x * blockDim.x;

    const int4* s4 = (const int4*)ei;  // src = ei[0..EE)
    for (int j = i; j < EE / 4; j += stride) {
        int4 s = __ldcs(&s4[j]);
        atomicAdd(&g_deg[s.x], 1);
        atomicAdd(&g_deg[s.y], 1);
        atomicAdd(&g_deg[s.z], 1);
        atomicAdd(&g_deg[s.w], 1);
    }

    // x layout: [B, T, N]; take t = T-1 slice for each b (stride-1 in n -> coalesced)
    const float* xl = x + (TT - 1) * NN;
    for (int n = i; n < NN; n += stride) {
        float4 a, b;
        a.x = xl[0 * TT * NN + n];
        a.y = xl[1 * TT * NN + n];
        a.z = xl[2 * TT * NN + n];
        a.w = xl[3 * TT * NN + n];
        g_xt[2 * n] = a;
        b.x = xl[4 * TT * NN + n];
        b.y = xl[5 * TT * NN + n];
        b.z = xl[6 * TT * NN + n];
        b.w = xl[7 * TT * NN + n];
        g_xt[2 * n + 1] = b;
    }
}

// ---------------------------------------------------------------------------
// K2: dinv = rsqrt(deg); gth = f16(dinv * xt); zero acch AND deg (self-clean
// for the next graph replay -> no memset node needed)
__global__ void k_dinv() {
    int i = blockIdx.x * blockDim.x + threadIdx.x;
    int stride = gridDim.x * blockDim.x;
    uint4 z4 = make_uint4(0u, 0u, 0u, 0u);
    for (int n = i; n < NN; n += stride) {
        int d = g_deg[n];
        g_deg[n] = 0;                       // reset for next replay
        float dv = (d > 0) ? rsqrtf((float)d) : 0.f;
        g_dinv[n] = dv;
        float4 a = g_xt[2 * n];
        float4 b = g_xt[2 * n + 1];
        __half2 h0 = __floats2half2_rn(a.x * dv, a.y * dv);
        __half2 h1 = __floats2half2_rn(a.z * dv, a.w * dv);
        __half2 h2 = __floats2half2_rn(b.x * dv, b.y * dv);
        __half2 h3 = __floats2half2_rn(b.z * dv, b.w * dv);
        uint4 p;
        p.x = *(unsigned int*)&h0;
        p.y = *(unsigned int*)&h1;
        p.z = *(unsigned int*)&h2;
        p.w = *(unsigned int*)&h3;
        g_gth[n] = p;
        g_acch[n] = z4;
    }
}

// ---------------------------------------------------------------------------
// K3: main edge scatter: acc[dst][0..7] += gt[src][0..7] via one 16B f16x2 RED
__global__ void k_scatter(const int* __restrict__ ei) {
    int i = blockIdx.x * blockDim.x + threadIdx.x;
    int stride = gridDim.x * blockDim.x;
    const int4* s4 = (const int4*)ei;         // src
    const int4* d4 = (const int4*)(ei + EE);  // dst
    for (int j = i; j < EE / 4; j += stride) {
        int4 s = __ldcs(&s4[j]);
        int4 d = __ldcs(&d4[j]);
        uint4 a0 = __ldg(&g_gth[s.x]);
        uint4 a1 = __ldg(&g_gth[s.y]);
        uint4 a2 = __ldg(&g_gth[s.z]);
        uint4 a3 = __ldg(&g_gth[s.w]);
        red_add_v4h2(&g_acch[d.x], a0);
        red_add_v4h2(&g_acch[d.y], a1);
        red_add_v4h2(&g_acch[d.z], a2);
        red_add_v4h2(&g_acch[d.w], a3);
    }
}

// ---------------------------------------------------------------------------
// K4: gate math body ONLY (no fence/counter/convergence — kernel boundary is
// the sync). Each block stores 128 partials (plain STG) and exits.
// Warp map: slot = lane>>2 (== batch b), hg = (lane&3)*4 -> each warp's 32
// lanes cover the 128 distinct (b,h) cells with 4 accumulators each.
__global__ void __launch_bounds__(CT)
k_combine(const float* __restrict__ wxz, const float* __restrict__ bxz,
          const float* __restrict__ bhz, const float* __restrict__ wxh,
          const float* __restrict__ bxh, const float* __restrict__ bhh) {
    const int t    = threadIdx.x;
    const int lane = t & 31;
    const int warp = t >> 5;               // 0..7
    const int slot = lane >> 2;            // 0..7 == batch b (invariant)
    const int hg   = (lane & 3) * 4;       // h base: 0,4,8,12

    // Stage weights in smem once per block (z-side pre-halved for tanh(za/2))
    __shared__ float swz0[NH], swz1[NH], sbz[NH], swh0[NH], swh1[NH], sbh[NH];
    if (t < NH) {
        swz0[t] = 0.5f * wxz[t];
        swz1[t] = 0.5f * wxz[NH + t];
        sbz[t]  = 0.5f * (bxz[t] + bhz[t]);
        swh0[t] = wxh[t];
        swh1[t] = wxh[NH + t];
        sbh[t]  = bxh[t] + bhh[t];
    }
    __syncthreads();

    float w0z[4], w1z[4], bz[4], w0h[4], w1h[4], bh[4];
#pragma unroll
    for (int j = 0; j < 4; j++) {
        w0z[j] = swz0[hg + j];  w1z[j] = swz1[hg + j];  bz[j] = sbz[hg + j];
        w0h[j] = swh0[hg + j];  w1h[j] = swh1[hg + j];  bh[j] = sbh[hg + j];
    }

    const int warp_g      = (blockIdx.x * CT + t) >> 5;
    const int total_warps = (CB * CT) >> 5;                  // 9472
    const int stride_idx  = total_warps * 8;                 // 75776, multiple of 8
    const int start       = warp_g * 8 + slot;               // < 75776 -> >=1 iter
    const int n_iter      = (NN * NB - 1 - start) / stride_idx + 1;  // 5 or 6

    const float*  p_x = (const float*)g_xt + start;
    const __half* p_a = (const __half*)g_acch + start;
    const float*  p_d = g_dinv + (start >> 3);
    const int     dstep = stride_idx >> 3;

    float acc[4] = {0.f, 0.f, 0.f, 0.f};
#pragma unroll 6
    for (int it = 0; it < n_iter; ++it) {
        float xv  = *p_x;
        float av  = __half2float(*p_a);
        float dv  = *p_d;
        p_x += stride_idx;  p_a += stride_idx;  p_d += dstep;
        float lxv = -dv * av;
#pragma unroll
        for (int j = 0; j < 4; j++) {
            float u = fmaf(xv, w0z[j], fmaf(lxv, w1z[j], bz[j]));
            float a = fmaf(xv, w0h[j], fmaf(lxv, w1h[j], bh[j]));
            // (1 - sigmoid(2u)) * tanh(a) = (0.5 - 0.5*tanh(u)) * tanh(a)
            acc[j] += fmaf(-0.5f, tanh_fast(u), 0.5f) * tanh_fast(a);
        }
    }

    // Atomic-free block reduction: each warp writes its 128 cells to a private row.
    __shared__ float sred[CT / 32][NB * NH];   // 8 x 128
#pragma unroll
    for (int j = 0; j < 4; j++) sred[warp][slot * NH + hg + j] = acc[j];
    __syncthreads();

    if (t < NB * NH) {
        float s = 0.f;
#pragma unroll
        for (int w = 0; w < CT / 32; w++) s += sred[w][t];
        g_part[blockIdx.x * 128 + t] = s;      // plain coalesced store; kernel exits
    }
}

// ---------------------------------------------------------------------------
// K5: reduce CB x 128 partials + ReLU-mean-linear head.
// 1024 threads: 8 threads per (b,h) cell -> 148 loads each, unroll-8 MLP.
__global__ void __launch_bounds__(1024)
k_final(const float* __restrict__ wlin, const float* __restrict__ blin,
        float* __restrict__ out) {
    const int t    = threadIdx.x;
    const int part = t >> 7;       // 0..7
    const int cell = t & 127;

    __shared__ float s8[8][NB * NH];
    __shared__ float sfin[NB * NH];

    float s = 0.f;
    const float* p = g_part + cell;
#pragma unroll 8
    for (int i = part; i < CB; i += 8) s += __ldcg(p + i * 128);
    s8[part][cell] = s;
    __syncthreads();

    if (t < NB * NH) {
        float tot = 0.f;
#pragma unroll
        for (int w = 0; w < 8; w++) tot += s8[w][t];
        float m = tot * (1.f / (float)NN);
        sfin[t] = fmaxf(m, 0.f) * wlin[t & (NH - 1)];
    }
    __syncthreads();

    if (t < NB) {
        float o = 0.f;
#pragma unroll
        for (int h = 0; h < NH; h++) o += sfin[t * NH + h];
        out[t] = o + blin[0];
    }
}

// ---------------------------------------------------------------------------
extern "C" void kernel_launch(void* const* d_in, const int* in_sizes, int n_in,
                              void* d_out, int out_size) {
    const float* x    = (const float*)d_in[0];  // [B,T,N,1]
    const int*   ei   = (const int*)d_in[1];    // [2,E]
    const float* wxz  = (const float*)d_in[2];  // [2,16]
    const float* bxz  = (const float*)d_in[3];
    const float* bhz  = (const float*)d_in[4];
    const float* wxh  = (const float*)d_in[5];
    const float* bxh  = (const float*)d_in[6];
    const float* bhh  = (const float*)d_in[7];
    const float* wlin = (const float*)d_in[8];  // [1,16]
    const float* blin = (const float*)d_in[9];  // [1]
    float* out = (float*)d_out;                 // [8]

    // g_deg is zero at module load and self-cleaned by k_dinv each run:
    // no memset node required.
    k_deg_xt<<<1184, 256>>>(ei, x);
    k_dinv<<<296, 256>>>();
    k_scatter<<<1184, 256>>>(ei);
    k_combine<<<CB, CT>>>(wxz, bxz, bhz, wxh, bxh, bhh);
    k_final<<<1, 1024>>>(wlin, blin, out);
}

// round 17
// speedup vs baseline: 1.1621x; 1.1621x over previous
#include <cuda_runtime.h>
#include <cuda_fp16.h>
#include <cstdint>

// Problem constants (fixed shapes)
#define NN 50000      // nodes
#define EE 1600000    // edges
#define TT 6          // time steps
#define NB 8          // batch
#define NH 16         // hidden

#define CB 592        // combine blocks (one full wave at 4/SM, 48-52 regs)
#define CT 256        // combine threads/block

// Scratch (device globals — no allocation allowed).
// g_deg starts zeroed (module load) and is RE-ZEROED by k_dinv each run,
// so the graph needs no memset node. Same self-cleaning pattern as g_acch.
__device__ int          g_deg[NN];
__device__ float        g_dinv[NN];
__device__ float4       g_xt[NN * 2];      // x[b, T-1, n] transposed to [n][8] (fp32)
__device__ uint4        g_gth[NN];         // dinv[n] * xt[n][b], packed 8 x f16
__device__ uint4        g_acch[NN];        // scatter accumulator, 8 x f16 per node
__device__ float        g_part[CB * 128];  // per-block partial (b,h) sums

// ---------------------------------------------------------------------------
__device__ __forceinline__ float tanh_fast(float x) {
    float y;
    asm("tanh.approx.f32 %0, %1;" : "=f"(y) : "f"(x));
    return y;
}

__device__ __forceinline__ void red_add_v4h2(uint4* addr, uint4 v) {
    asm volatile("red.global.add.noftz.v4.f16x2 [%0], {%1, %2, %3, %4};"
                 :: "l"(addr), "r"(v.x), "r"(v.y), "r"(v.z), "r"(v.w)
                 : "memory");
}

// ---------------------------------------------------------------------------
// K1: degree histogram (src column) + transpose last-timestep x to [n][8]
__global__ void k_deg_xt(const int* __restrict__ ei, const float* __restrict__ x) {
    int i = blockIdx.x * blockDim.x + threadIdx.x;
    int stride = gridDim.x * blockDim.x;

    const int4* s4 = (const int4*)ei;  // src = ei[0..EE)
    for (int j = i; j < EE / 4; j += stride) {
        int4 s = __ldcs(&s4[j]);
        atomicAdd(&g_deg[s.x], 1);
        atomicAdd(&g_deg[s.y], 1);
        atomicAdd(&g_deg[s.z], 1);
        atomicAdd(&g_deg[s.w], 1);
    }

    // x layout: [B, T, N]; take t = T-1 slice for each b (stride-1 in n -> coalesced)
    const float* xl = x + (TT - 1) * NN;
    for (int n = i; n < NN; n += stride) {
        float4 a, b;
        a.x = xl[0 * TT * NN + n];
        a.y = xl[1 * TT * NN + n];
        a.z = xl[2 * TT * NN + n];
        a.w = xl[3 * TT * NN + n];
        g_xt[2 * n] = a;
        b.x = xl[4 * TT * NN + n];
        b.y = xl[5 * TT * NN + n];
        b.z = xl[6 * TT * NN + n];
        b.w = xl[7 * TT * NN + n];
        g_xt[2 * n + 1] = b;
    }
}

// ---------------------------------------------------------------------------
// K2: dinv = rsqrt(deg); gth = f16(dinv * xt); zero acch AND deg (self-clean
// for the next graph replay -> no memset node needed)
__global__ void k_dinv() {
    int i = blockIdx.x * blockDim.x + threadIdx.x;
    int stride = gridDim.x * blockDim.x;
    uint4 z4 = make_uint4(0u, 0u, 0u, 0u);
    for (int n = i; n < NN; n += stride) {
        int d = g_deg[n];
        g_deg[n] = 0;                       // reset for next replay
        float dv = (d > 0) ? rsqrtf((float)d) : 0.f;
        g_dinv[n] = dv;
        float4 a = g_xt[2 * n];
        float4 b = g_xt[2 * n + 1];
        __half2 h0 = __floats2half2_rn(a.x * dv, a.y * dv);
        __half2 h1 = __floats2half2_rn(a.z * dv, a.w * dv);
        __half2 h2 = __floats2half2_rn(b.x * dv, b.y * dv);
        __half2 h3 = __floats2half2_rn(b.z * dv, b.w * dv);
        uint4 p;
        p.x = *(unsigned int*)&h0;
        p.y = *(unsigned int*)&h1;
        p.z = *(unsigned int*)&h2;
        p.w = *(unsigned int*)&h3;
        g_gth[n] = p;
        g_acch[n] = z4;
    }
}

// ---------------------------------------------------------------------------
// K3: main edge scatter: acc[dst][0..7] += gt[src][0..7] via one 16B f16x2 RED
__global__ void k_scatter(const int* __restrict__ ei) {
    int i = blockIdx.x * blockDim.x + threadIdx.x;
    int stride = gridDim.x * blockDim.x;
    const int4* s4 = (const int4*)ei;         // src
    const int4* d4 = (const int4*)(ei + EE);  // dst
    for (int j = i; j < EE / 4; j += stride) {
        int4 s = __ldcs(&s4[j]);
        int4 d = __ldcs(&d4[j]);
        uint4 a0 = __ldg(&g_gth[s.x]);
        uint4 a1 = __ldg(&g_gth[s.y]);
        uint4 a2 = __ldg(&g_gth[s.z]);
        uint4 a3 = __ldg(&g_gth[s.w]);
        red_add_v4h2(&g_acch[d.x], a0);
        red_add_v4h2(&g_acch[d.y], a1);
        red_add_v4h2(&g_acch[d.z], a2);
        red_add_v4h2(&g_acch[d.w], a3);
    }
}

// ---------------------------------------------------------------------------
// K4: gate math body, SOFTWARE-PIPELINED: iteration i+1's loads issue before
// iteration i's compute block, so each warp overlaps one full compute block
// (~100cyc) with the L2 latency of the next loads. No fence/counter: each
// block stores 128 partials (plain STG) and exits.
// Warp map: slot = lane>>2 (== batch b), hg = (lane&3)*4 -> each warp's 32
// lanes cover the 128 distinct (b,h) cells with 4 accumulators each.
__global__ void __launch_bounds__(CT)
k_combine(const float* __restrict__ wxz, const float* __restrict__ bxz,
          const float* __restrict__ bhz, const float* __restrict__ wxh,
          const float* __restrict__ bxh, const float* __restrict__ bhh) {
    const int t    = threadIdx.x;
    const int lane = t & 31;
    const int warp = t >> 5;               // 0..7
    const int slot = lane >> 2;            // 0..7 == batch b (invariant)
    const int hg   = (lane & 3) * 4;       // h base: 0,4,8,12

    // Stage weights in smem once per block (z-side pre-halved for tanh(za/2))
    __shared__ float swz0[NH], swz1[NH], sbz[NH], swh0[NH], swh1[NH], sbh[NH];
    if (t < NH) {
        swz0[t] = 0.5f * wxz[t];
        swz1[t] = 0.5f * wxz[NH + t];
        sbz[t]  = 0.5f * (bxz[t] + bhz[t]);
        swh0[t] = wxh[t];
        swh1[t] = wxh[NH + t];
        sbh[t]  = bxh[t] + bhh[t];
    }
    __syncthreads();

    float w0z[4], w1z[4], bz[4], w0h[4], w1h[4], bh[4];
#pragma unroll
    for (int j = 0; j < 4; j++) {
        w0z[j] = swz0[hg + j];  w1z[j] = swz1[hg + j];  bz[j] = sbz[hg + j];
        w0h[j] = swh0[hg + j];  w1h[j] = swh1[hg + j];  bh[j] = sbh[hg + j];
    }

    const int warp_g      = (blockIdx.x * CT + t) >> 5;
    const int total_warps = (CB * CT) >> 5;                  // 4736
    const int stride_idx  = total_warps * 8;                 // 37888, multiple of 8
    const int start       = warp_g * 8 + slot;               // < 37888 -> >=1 iter
    const int n_iter      = (NN * NB - 1 - start) / stride_idx + 1;  // 10 or 11

    const float*  p_x = (const float*)g_xt + start;
    const __half* p_a = (const __half*)g_acch + start;
    const float*  p_d = g_dinv + (start >> 3);
    const int     dstep = stride_idx >> 3;

    float acc[4] = {0.f, 0.f, 0.f, 0.f};

    // Pipeline prologue: first iteration's loads in flight
    float xv = *p_x;
    float av = __half2float(*p_a);
    float dv = *p_d;

    for (int it = 0; it < n_iter - 1; ++it) {
        p_x += stride_idx;  p_a += stride_idx;  p_d += dstep;
        // Issue NEXT iteration's loads before this iteration's compute
        float xv_n = *p_x;
        float av_n = __half2float(*p_a);
        float dv_n = *p_d;

        float lxv = -dv * av;
#pragma unroll
        for (int j = 0; j < 4; j++) {
            float u = fmaf(xv, w0z[j], fmaf(lxv, w1z[j], bz[j]));
            float a = fmaf(xv, w0h[j], fmaf(lxv, w1h[j], bh[j]));
            // (1 - sigmoid(2u)) * tanh(a) = (0.5 - 0.5*tanh(u)) * tanh(a)
            acc[j] += fmaf(-0.5f, tanh_fast(u), 0.5f) * tanh_fast(a);
        }
        xv = xv_n;  av = av_n;  dv = dv_n;
    }
    {   // Epilogue: last iteration
        float lxv = -dv * av;
#pragma unroll
        for (int j = 0; j < 4; j++) {
            float u = fmaf(xv, w0z[j], fmaf(lxv, w1z[j], bz[j]));
            float a = fmaf(xv, w0h[j], fmaf(lxv, w1h[j], bh[j]));
            acc[j] += fmaf(-0.5f, tanh_fast(u), 0.5f) * tanh_fast(a);
        }
    }

    // Atomic-free block reduction: each warp writes its 128 cells to a private row.
    __shared__ float sred[CT / 32][NB * NH];   // 8 x 128
#pragma unroll
    for (int j = 0; j < 4; j++) sred[warp][slot * NH + hg + j] = acc[j];
    __syncthreads();

    if (t < NB * NH) {
        float s = 0.f;
#pragma unroll
        for (int w = 0; w < CT / 32; w++) s += sred[w][t];
        g_part[blockIdx.x * 128 + t] = s;      // plain coalesced store; kernel exits
    }
}

// ---------------------------------------------------------------------------
// K5: reduce CB x 128 partials + ReLU-mean-linear head.
// 1024 threads: 8 threads per (b,h) cell -> 74 loads each, unroll-8 MLP.
__global__ void __launch_bounds__(1024)
k_final(const float* __restrict__ wlin, const float* __restrict__ blin,
        float* __restrict__ out) {
    const int t    = threadIdx.x;
    const int part = t >> 7;       // 0..7
    const int cell = t & 127;

    __shared__ float s8[8][NB * NH];
    __shared__ float sfin[NB * NH];

    float s = 0.f;
    const float* p = g_part + cell;
#pragma unroll 8
    for (int i = part; i < CB; i += 8) s += __ldcg(p + i * 128);
    s8[part][cell] = s;
    __syncthreads();

    if (t < NB * NH) {
        float tot = 0.f;
#pragma unroll
        for (int w = 0; w < 8; w++) tot += s8[w][t];
        float m = tot * (1.f / (float)NN);
        sfin[t] = fmaxf(m, 0.f) * wlin[t & (NH - 1)];
    }
    __syncthreads();

    if (t < NB) {
        float o = 0.f;
#pragma unroll
        for (int h = 0; h < NH; h++) o += sfin[t * NH + h];
        out[t] = o + blin[0];
    }
}

// ---------------------------------------------------------------------------
extern "C" void kernel_launch(void* const* d_in, const int* in_sizes, int n_in,
                              void* d_out, int out_size) {
    const float* x    = (const float*)d_in[0];  // [B,T,N,1]
    const int*   ei   = (const int*)d_in[1];    // [2,E]
    const float* wxz  = (const float*)d_in[2];  // [2,16]
    const float* bxz  = (const float*)d_in[3];
    const float* bhz  = (const float*)d_in[4];
    const float* wxh  = (const float*)d_in[5];
    const float* bxh  = (const float*)d_in[6];
    const float* bhh  = (const float*)d_in[7];
    const float* wlin = (const float*)d_in[8];  // [1,16]
    const float* blin = (const float*)d_in[9];  // [1]
    float* out = (float*)d_out;                 // [8]

    // g_deg is zero at module load and self-cleaned by k_dinv each run:
    // no memset node required.
    k_deg_xt<<<1184, 256>>>(ei, x);
    k_dinv<<<296, 256>>>();
    k_scatter<<<1184, 256>>>(ei);
    k_combine<<<CB, CT>>>(wxz, bxz, bhz, wxh, bxh, bhh);
    k_final<<<1, 1024>>>(wlin, blin, out);
}